// round 7
// baseline (speedup 1.0000x reference)
#include <cuda_runtime.h>
#include <math.h>

// ---------------- scratch ----------------
__device__ float g_bufA[800L*64*42*42];   // conv1 out
__device__ float g_bufB[800L*64*21*21];   // conv2 out
__device__ float g_bufC[800L*64*11*11];   // conv3 out
__device__ float g_bufD[800L*2304];       // conv4 out (embeddings)
__device__ float g_protos[8*5*2304];
__device__ float g_protoInv[8*5];
// prepacked weights, chunked: [chunk][cout][c_within][9]
__device__ float g_wp1[64*3*9];
__device__ float g_wp2[64*64*9];
__device__ float g_wp3[64*64*9];
__device__ float g_wp4[64*64*9];

// ---------------- weight prepack: OIHW -> [chunk][cout][cw][9] -------------
__global__ void prepack_kernel(const float* __restrict__ w, float* __restrict__ wp,
                               int CIN, int CK)
{
    int gid = blockIdx.x * 256 + threadIdx.x;
    int total = CIN * 64 * 9;
    if (gid >= total) return;
    // destination indexing
    int per_chunk = 64 * CK * 9;
    int q    = gid / per_chunk;
    int rem  = gid - q*per_chunk;
    int cout = rem / (CK*9);
    int r2   = rem - cout*(CK*9);
    int cw   = r2 / 9;
    int k    = r2 - cw*9;
    wp[gid] = w[(cout*CIN + q*CK + cw)*9 + k];
}

// ---------------- R1 conv kernel + 2-blocks/SM launch bound ----------------
// Block: one image n, OYT output rows, all 64 couts.
// Shared: zero-padded input tile (CK cins x (2*OYT+1) rows x (2*OW+1) cols)
//         + weight chunk [cout][c][k] (linear copy from prepacked source).
// Thread: 8 couts x TPOS strided positions.
template<int CIN, int H, int OH, int PADLOW, int OYT, int TPOS, int CK, int PTHREADS>
__global__ void __launch_bounds__(PTHREADS*8, 2)
conv_s2_kernel(const float* __restrict__ in, const float* __restrict__ wp,
               const float* __restrict__ bias, float* __restrict__ out)
{
    constexpr int W = H, OW = OH;
    constexpr int RP = 2*OYT + 1;
    constexpr int WP = 2*OW + 1;
    constexpr int IN_SZ = CK*RP*WP;
    constexpr int W_SZ  = 64*CK*9;
    constexpr int NPOS  = OYT*OW;
    constexpr int NT    = PTHREADS*8;

    __shared__ float s_in[IN_SZ];
    __shared__ float s_w[W_SZ];

    const int n   = blockIdx.x;
    const int oy0 = blockIdx.y * OYT;
    const int tid = threadIdx.x;
    const int px  = tid % PTHREADS;
    const int cy  = tid / PTHREADS;     // cout group 0..7

    int  baseoff[TPOS], oyl_arr[TPOS], ox_arr[TPOS];
    bool valid[TPOS];
#pragma unroll
    for (int p = 0; p < TPOS; p++) {
        int pos = px + p*PTHREADS;               // strided -> adjacent lanes adjacent
        valid[p] = pos < NPOS;
        if (pos >= NPOS) pos = NPOS - 1;
        int oyl = pos / OW;
        int ox  = pos - oyl*OW;
        oyl_arr[p] = oyl; ox_arr[p] = ox;
        baseoff[p] = (2*oyl)*WP + 2*ox;
    }

    float acc[8][TPOS];
#pragma unroll
    for (int i = 0; i < 8; i++)
#pragma unroll
        for (int j = 0; j < TPOS; j++) acc[i][j] = 0.f;

    for (int c0 = 0; c0 < CIN; c0 += CK) {
        // stage zero-padded input tile
        for (int idx = tid; idx < IN_SZ; idx += NT) {
            int c   = idx / (RP*WP);
            int rem = idx - c*(RP*WP);
            int r   = rem / WP;
            int s   = rem - r*WP;
            int gr  = 2*oy0 + r - PADLOW;
            int gc  = s - PADLOW;
            float v = 0.f;
            if (gr >= 0 && gr < H && gc >= 0 && gc < W)
                v = in[((n*CIN + c0 + c)*H + gr)*W + gc];
            s_in[idx] = v;
        }
        // stage weight chunk: straight linear copy (prepacked [cout][c][k])
        {
            const float* src = wp + (c0/CK)*(64*CK*9);
            for (int idx = tid; idx < W_SZ; idx += NT)
                s_w[idx] = src[idx];
        }
        __syncthreads();

#pragma unroll
        for (int c = 0; c < CK; c++) {
            float xin[TPOS][9];
#pragma unroll
            for (int p = 0; p < TPOS; p++) {
                const float* bp = &s_in[c*(RP*WP) + baseoff[p]];
#pragma unroll
                for (int ky = 0; ky < 3; ky++)
#pragma unroll
                    for (int kx = 0; kx < 3; kx++)
                        xin[p][ky*3 + kx] = bp[ky*WP + kx];
            }
#pragma unroll
            for (int co = 0; co < 8; co++) {
                const float* wq = &s_w[((cy*8 + co)*CK + c)*9];
                float wl[9];
#pragma unroll
                for (int k = 0; k < 9; k++) wl[k] = wq[k];
#pragma unroll
                for (int p = 0; p < TPOS; p++) {
                    float a = acc[co][p];
#pragma unroll
                    for (int k = 0; k < 9; k++) a = fmaf(wl[k], xin[p][k], a);
                    acc[co][p] = a;
                }
            }
        }
        __syncthreads();
    }

    const int oy_valid = (OH - oy0 < OYT) ? (OH - oy0) : OYT;
#pragma unroll
    for (int co = 0; co < 8; co++) {
        const int cout = cy*8 + co;
        const float bb = bias[cout];
#pragma unroll
        for (int p = 0; p < TPOS; p++) {
            if (valid[p] && oyl_arr[p] < oy_valid) {
                float v = acc[co][p] + bb;
                out[((n*64 + cout)*OH + oy0 + oyl_arr[p])*OW + ox_arr[p]] = v > 0.f ? v : 0.f;
            }
        }
    }
}

// ---------------- prototypes + inverse norms ----------------
__global__ void protos_kernel(const float* __restrict__ emb, const int* __restrict__ y,
                              float* __restrict__ protos, float* __restrict__ protoInv)
{
    const int b = blockIdx.x / 5, c = blockIdx.x % 5;
    const int tid = threadIdx.x;                   // 256
    __shared__ int sels[25];
    if (tid < 25) sels[tid] = ((y[b*25 + tid] % 5) == c) ? 1 : 0;
    __syncthreads();

    float sq = 0.f;
    for (int d = tid; d < 2304; d += 256) {
        float v = 0.f;
#pragma unroll
        for (int s = 0; s < 25; s++)
            if (sels[s]) v += emb[(b*25 + s)*2304 + d];
        v = v / 5.0f;                              // CAP = 5
        protos[(b*5 + c)*2304 + d] = v;
        sq += v*v;
    }
    __shared__ float red[256];
    red[tid] = sq; __syncthreads();
    for (int s = 128; s > 0; s >>= 1) {
        if (tid < s) red[tid] += red[tid + s];
        __syncthreads();
    }
    if (tid == 0) protoInv[b*5 + c] = 1.f / fmaxf(sqrtf(red[0]), 1e-8f);
}

// ---------------- cosine logits ----------------
__global__ void preds_kernel(const float* __restrict__ emb, const float* __restrict__ protos,
                             const float* __restrict__ protoInv, float* __restrict__ out)
{
    const int b = blockIdx.x / 75, t = blockIdx.x % 75;
    const int tid = threadIdx.x;                   // 256
    float dot[5] = {0,0,0,0,0};
    float nsq = 0.f;
    const float* e = emb + (size_t)(200 + b*75 + t)*2304;
    for (int d = tid; d < 2304; d += 256) {
        float ev = e[d];
        nsq += ev*ev;
#pragma unroll
        for (int c = 0; c < 5; c++)
            dot[c] = fmaf(ev, protos[(b*5 + c)*2304 + d], dot[c]);
    }
    __shared__ float red[256];
    __shared__ float res[6];
    for (int q = 0; q < 6; q++) {
        red[tid] = (q == 0) ? nsq : dot[q-1];
        __syncthreads();
        for (int s = 128; s > 0; s >>= 1) {
            if (tid < s) red[tid] += red[tid + s];
            __syncthreads();
        }
        if (tid == 0) res[q] = red[0];
        __syncthreads();
    }
    if (tid < 5) {
        float inv_t = 1.f / fmaxf(sqrtf(res[0]), 1e-8f);
        out[(b*75 + t)*5 + tid] = res[1 + tid] * inv_t * protoInv[b*5 + tid];
    }
}

// ---------------- launch ----------------
extern "C" void kernel_launch(void* const* d_in, const int* in_sizes, int n_in,
                              void* d_out, int out_size)
{
    const float* xs = (const float*)d_in[0];
    const float* xt = (const float*)d_in[1];
    const int*   y  = (const int*)  d_in[2];
    const float* W1 = (const float*)d_in[3];
    const float* b1 = (const float*)d_in[4];
    const float* W2 = (const float*)d_in[5];
    const float* b2 = (const float*)d_in[6];
    const float* W3 = (const float*)d_in[7];
    const float* b3 = (const float*)d_in[8];
    const float* W4 = (const float*)d_in[9];
    const float* b4 = (const float*)d_in[10];
    float* out = (float*)d_out;

    float *bufA, *bufB, *bufC, *bufD, *pr, *pi;
    float *wp1, *wp2, *wp3, *wp4;
    cudaGetSymbolAddress((void**)&bufA, g_bufA);
    cudaGetSymbolAddress((void**)&bufB, g_bufB);
    cudaGetSymbolAddress((void**)&bufC, g_bufC);
    cudaGetSymbolAddress((void**)&bufD, g_bufD);
    cudaGetSymbolAddress((void**)&pr,   g_protos);
    cudaGetSymbolAddress((void**)&pi,   g_protoInv);
    cudaGetSymbolAddress((void**)&wp1,  g_wp1);
    cudaGetSymbolAddress((void**)&wp2,  g_wp2);
    cudaGetSymbolAddress((void**)&wp3,  g_wp3);
    cudaGetSymbolAddress((void**)&wp4,  g_wp4);

    // prepack weights (tiny; CK must match conv launches below)
    prepack_kernel<<<(64*3*9  + 255)/256, 256>>>(W1, wp1, 3, 3);
    prepack_kernel<<<(64*64*9 + 255)/256, 256>>>(W2, wp2, 64, 8);
    prepack_kernel<<<(64*64*9 + 255)/256, 256>>>(W3, wp3, 64, 8);
    prepack_kernel<<<(64*64*9 + 255)/256, 256>>>(W4, wp4, 64, 8);

    // <CIN,H,OH,PADLOW, OYT,TPOS,CK, PTHREADS>  — exact R1 configs
    // conv1: 3->64, 84->42, pad_low=0
    conv_s2_kernel<3,84,42,0, 3,4,3, 32><<<dim3(200,14), 256>>>(xs, wp1, b1, bufA);
    conv_s2_kernel<3,84,42,0, 3,4,3, 32><<<dim3(600,14), 256>>>(xt, wp1, b1, bufA + (size_t)200*64*42*42);
    // conv2: 64->64, 42->21, pad_low=0
    conv_s2_kernel<64,42,21,0, 6,4,8, 32><<<dim3(800,4), 256>>>(bufA, wp2, b2, bufB);
    // conv3: 64->64, 21->11, pad_low=1
    conv_s2_kernel<64,21,11,1, 11,4,8, 31><<<dim3(800,1), 248>>>(bufB, wp3, b3, bufC);
    // conv4: 64->64, 11->6, pad_low=1
    conv_s2_kernel<64,11,6,1, 6,2,8, 18><<<dim3(800,1), 144>>>(bufC, wp4, b4, bufD);
    // head
    protos_kernel<<<40, 256>>>(bufD, y, pr, pi);
    preds_kernel<<<600, 256>>>(bufD, pr, pi, out);
}

// round 9
// speedup vs baseline: 2.1067x; 2.1067x over previous
#include <cuda_runtime.h>
#include <math.h>
#include <stdint.h>

// ---------------- scratch ----------------
__device__ float g_bufA[800L*64*42*42];   // conv1 out (NHWC: [n][y][x][cin])
__device__ float g_bufB[800L*64*21*21];   // conv2 out (NCHW)
__device__ float g_bufC[800L*64*11*11];   // conv3 out (NCHW)
__device__ float g_bufD[800L*2304];       // conv4 out (embeddings)
__device__ float g_protos[8*5*2304];
__device__ float g_protoInv[8*5];
// conv2 weights prepacked for tensor path: [tap(9)][cin(64)][cout(64)], tf32-rounded
__device__ float g_w2t[9*64*64];

__device__ __forceinline__ float tf32_rna(float x) {
    uint32_t r; asm("cvt.rna.tf32.f32 %0, %1;" : "=r"(r) : "f"(x));
    return __uint_as_float(r);
}

// ---------------- conv2 weight prepack ----------------
__global__ void prepack_w2(const float* __restrict__ w2, float* __restrict__ wt)
{
    int gid = blockIdx.x * 256 + threadIdx.x;          // 9*4096 = 36864
    if (gid >= 9*4096) return;
    int tap  = gid >> 12;
    int r    = gid & 4095;
    int cin  = r >> 6;
    int cout = r & 63;
    wt[gid] = tf32_rna(w2[(cout*64 + cin)*9 + tap]);
}

// ---------------- scalar stride-2 conv (EXACT R1) + optional NHWC out ------
template<int CIN, int H, int OH, int PADLOW, int OYT, int TPOS, int CK, int PTHREADS, bool NHWC>
__global__ void __launch_bounds__(PTHREADS*8)
conv_s2_kernel(const float* __restrict__ in, const float* __restrict__ wgt,
               const float* __restrict__ bias, float* __restrict__ out)
{
    constexpr int W = H, OW = OH;
    constexpr int RP = 2*OYT + 1;
    constexpr int WP = 2*OW + 1;
    constexpr int IN_SZ = CK*RP*WP;
    constexpr int W_SZ  = 64*CK*9;
    constexpr int NPOS  = OYT*OW;
    constexpr int NT    = PTHREADS*8;

    __shared__ float s_in[IN_SZ];
    __shared__ float s_w[W_SZ];

    const int n   = blockIdx.x;
    const int oy0 = blockIdx.y * OYT;
    const int tid = threadIdx.x;
    const int px  = tid % PTHREADS;
    const int cy  = tid / PTHREADS;

    int  baseoff[TPOS], oyl_arr[TPOS], ox_arr[TPOS];
    bool valid[TPOS];
#pragma unroll
    for (int p = 0; p < TPOS; p++) {
        int pos = px + p*PTHREADS;
        valid[p] = pos < NPOS;
        if (pos >= NPOS) pos = NPOS - 1;
        int oyl = pos / OW;
        int ox  = pos - oyl*OW;
        oyl_arr[p] = oyl; ox_arr[p] = ox;
        baseoff[p] = (2*oyl)*WP + 2*ox;
    }

    float acc[8][TPOS];
#pragma unroll
    for (int i = 0; i < 8; i++)
#pragma unroll
        for (int j = 0; j < TPOS; j++) acc[i][j] = 0.f;

    for (int c0 = 0; c0 < CIN; c0 += CK) {
        for (int idx = tid; idx < IN_SZ; idx += NT) {
            int c   = idx / (RP*WP);
            int rem = idx - c*(RP*WP);
            int r   = rem / WP;
            int s   = rem - r*WP;
            int gr  = 2*oy0 + r - PADLOW;
            int gc  = s - PADLOW;
            float v = 0.f;
            if (gr >= 0 && gr < H && gc >= 0 && gc < W)
                v = in[((n*CIN + c0 + c)*H + gr)*W + gc];
            s_in[idx] = v;
        }
        for (int idx = tid; idx < W_SZ; idx += NT) {
            int cout = idx / (CK*9);
            int rem  = idx - cout*(CK*9);
            s_w[idx] = wgt[(cout*CIN + c0)*9 + rem];
        }
        __syncthreads();

#pragma unroll
        for (int c = 0; c < CK; c++) {
            float xin[TPOS][9];
#pragma unroll
            for (int p = 0; p < TPOS; p++) {
                const float* bp = &s_in[c*(RP*WP) + baseoff[p]];
#pragma unroll
                for (int ky = 0; ky < 3; ky++)
#pragma unroll
                    for (int kx = 0; kx < 3; kx++)
                        xin[p][ky*3 + kx] = bp[ky*WP + kx];
            }
#pragma unroll
            for (int co = 0; co < 8; co++) {
                const float* wq = &s_w[((cy*8 + co)*CK + c)*9];
                float wl[9];
#pragma unroll
                for (int k = 0; k < 9; k++) wl[k] = wq[k];
#pragma unroll
                for (int p = 0; p < TPOS; p++) {
                    float a = acc[co][p];
#pragma unroll
                    for (int k = 0; k < 9; k++) a = fmaf(wl[k], xin[p][k], a);
                    acc[co][p] = a;
                }
            }
        }
        __syncthreads();
    }

    const int oy_valid = (OH - oy0 < OYT) ? (OH - oy0) : OYT;
    if (NHWC) {
        float bz[8];
#pragma unroll
        for (int co = 0; co < 8; co++) bz[co] = bias[cy*8 + co];
#pragma unroll
        for (int p = 0; p < TPOS; p++) {
            if (valid[p] && oyl_arr[p] < oy_valid) {
                float4 v0, v1;
                v0.x = fmaxf(acc[0][p]+bz[0], 0.f); v0.y = fmaxf(acc[1][p]+bz[1], 0.f);
                v0.z = fmaxf(acc[2][p]+bz[2], 0.f); v0.w = fmaxf(acc[3][p]+bz[3], 0.f);
                v1.x = fmaxf(acc[4][p]+bz[4], 0.f); v1.y = fmaxf(acc[5][p]+bz[5], 0.f);
                v1.z = fmaxf(acc[6][p]+bz[6], 0.f); v1.w = fmaxf(acc[7][p]+bz[7], 0.f);
                float* op = &out[(((size_t)n*OH + oy0 + oyl_arr[p])*OW + ox_arr[p])*64 + cy*8];
                *(float4*)op       = v0;
                *(float4*)(op + 4) = v1;
            }
        }
    } else {
#pragma unroll
        for (int co = 0; co < 8; co++) {
            const int cout = cy*8 + co;
            const float bb = bias[cout];
#pragma unroll
            for (int p = 0; p < TPOS; p++) {
                if (valid[p] && oyl_arr[p] < oy_valid) {
                    float v = acc[co][p] + bb;
                    out[((n*64 + cout)*OH + oy0 + oyl_arr[p])*OW + ox_arr[p]] = v > 0.f ? v : 0.f;
                }
            }
        }
    }
}

// ---------------- conv2: mma.sync tf32 implicit GEMM -----------------------
// CTA: image n, 6 output rows -> M=128 (126 used), N=64, K=576 = 9 taps x 64 cin.
// 8 warps, each owns a 32x32 (MxN) tile. Per tap: stage A (128x64, pitch 68) +
// B (64x64, pitch 72), then 8 k-steps of m16n8k8 mma.
#define C2_AP 68
#define C2_BP 72
#define C2_SMEMF (128*C2_AP + 64*C2_BP + 64)

__global__ void __launch_bounds__(256)
conv2_mma(const float* __restrict__ in, const float* __restrict__ wt,
          const float* __restrict__ bias, float* __restrict__ out)
{
    extern __shared__ float smf[];
    float* sA = smf;                    // 128 x 68
    float* sB = smf + 128*C2_AP;        // 64 x 72
    float* sbias = sB + 64*C2_BP;       // 64

    const int tid  = threadIdx.x;
    const int wid  = tid >> 5;
    const int lane = tid & 31;
    const int n    = blockIdx.x;
    const int oy0  = blockIdx.y * 6;
    const int nrows = (21 - oy0 < 6) ? (21 - oy0) : 6;
    const int npos  = nrows * 21;

    if (tid < 64) sbias[tid] = bias[tid];

    const int wm = (wid & 3) * 32;      // warp M origin
    const int wn = (wid >> 2) * 32;     // warp N origin

    float c[2][4][4];
#pragma unroll
    for (int i = 0; i < 2; i++)
#pragma unroll
        for (int j = 0; j < 4; j++)
#pragma unroll
            for (int q = 0; q < 4; q++) c[i][j][q] = 0.f;

    // A staging: 2 threads per position, 32 cins each
    const int p2   = tid >> 1;
    const int half = tid & 1;
    const int oyl  = p2 / 21;
    const int oxp  = p2 - oyl*21;
    const bool pv  = p2 < npos;
    const int oy   = oy0 + oyl;

    for (int tap = 0; tap < 9; tap++) {
        const int ky = tap / 3, kx = tap - 3*(tap/3);
        const int ry = 2*oy + ky;       // pad_low = 0 for conv2
        const int rx = 2*oxp + kx;
        const bool v = pv && (ry < 42) && (rx < 42);
        const float* src = in + (((size_t)n*42 + ry)*42 + rx)*64 + half*32;
        float* dstA = sA + p2*C2_AP + half*32;
#pragma unroll
        for (int j = 0; j < 8; j++) {
            float4 x = v ? *(const float4*)(src + 4*j) : make_float4(0.f,0.f,0.f,0.f);
            x.x = tf32_rna(x.x); x.y = tf32_rna(x.y);
            x.z = tf32_rna(x.z); x.w = tf32_rna(x.w);
            *(float4*)(dstA + 4*j) = x;
        }
        {
            const float4* bsrc = (const float4*)(wt + tap*4096);
#pragma unroll
            for (int i = 0; i < 4; i++) {
                int idx = tid + i*256;          // 0..1023
                int row = idx >> 4, col4 = idx & 15;
                *(float4*)(sB + row*C2_BP + col4*4) = bsrc[idx];
            }
        }
        __syncthreads();

#pragma unroll
        for (int ks = 0; ks < 8; ks++) {
            const int k0 = ks*8;
            uint32_t a[2][4];
#pragma unroll
            for (int mi = 0; mi < 2; mi++) {
                const float* ap = sA + (wm + mi*16 + (lane>>2))*C2_AP + k0 + (lane&3);
                a[mi][0] = __float_as_uint(ap[0]);
                a[mi][1] = __float_as_uint(ap[8*C2_AP]);
                a[mi][2] = __float_as_uint(ap[4]);
                a[mi][3] = __float_as_uint(ap[8*C2_AP + 4]);
            }
            uint32_t b[4][2];
#pragma unroll
            for (int ni = 0; ni < 4; ni++) {
                const float* bp = sB + (k0 + (lane&3))*C2_BP + wn + ni*8 + (lane>>2);
                b[ni][0] = __float_as_uint(bp[0]);
                b[ni][1] = __float_as_uint(bp[4*C2_BP]);
            }
#pragma unroll
            for (int mi = 0; mi < 2; mi++)
#pragma unroll
                for (int ni = 0; ni < 4; ni++)
                    asm volatile(
                        "mma.sync.aligned.m16n8k8.row.col.f32.tf32.tf32.f32 "
                        "{%0,%1,%2,%3}, {%4,%5,%6,%7}, {%8,%9}, {%0,%1,%2,%3};"
                        : "+f"(c[mi][ni][0]), "+f"(c[mi][ni][1]),
                          "+f"(c[mi][ni][2]), "+f"(c[mi][ni][3])
                        : "r"(a[mi][0]), "r"(a[mi][1]), "r"(a[mi][2]), "r"(a[mi][3]),
                          "r"(b[ni][0]), "r"(b[ni][1]));
        }
        __syncthreads();
    }

    // epilogue: bias + relu, NCHW store
#pragma unroll
    for (int mi = 0; mi < 2; mi++) {
        const int r0 = wm + mi*16 + (lane>>2);
#pragma unroll
        for (int ni = 0; ni < 4; ni++) {
            const int c0 = wn + ni*8 + 2*(lane&3);
#pragma unroll
            for (int q = 0; q < 4; q++) {
                const int row = r0 + ((q >= 2) ? 8 : 0);
                const int col = c0 + (q & 1);
                if (row < npos) {
                    const int oy2 = oy0 + row/21, ox2 = row - 21*(row/21);
                    float vv = c[mi][ni][q] + sbias[col];
                    out[(((size_t)n*64 + col)*21 + oy2)*21 + ox2] = vv > 0.f ? vv : 0.f;
                }
            }
        }
    }
}

// ---------------- prototypes + inverse norms ----------------
__global__ void protos_kernel(const float* __restrict__ emb, const int* __restrict__ y,
                              float* __restrict__ protos, float* __restrict__ protoInv)
{
    const int b = blockIdx.x / 5, c = blockIdx.x % 5;
    const int tid = threadIdx.x;
    __shared__ int sels[25];
    if (tid < 25) sels[tid] = ((y[b*25 + tid] % 5) == c) ? 1 : 0;
    __syncthreads();

    float sq = 0.f;
    for (int d = tid; d < 2304; d += 256) {
        float v = 0.f;
#pragma unroll
        for (int s = 0; s < 25; s++)
            if (sels[s]) v += emb[(b*25 + s)*2304 + d];
        v = v / 5.0f;
        protos[(b*5 + c)*2304 + d] = v;
        sq += v*v;
    }
    __shared__ float red[256];
    red[tid] = sq; __syncthreads();
    for (int s = 128; s > 0; s >>= 1) {
        if (tid < s) red[tid] += red[tid + s];
        __syncthreads();
    }
    if (tid == 0) protoInv[b*5 + c] = 1.f / fmaxf(sqrtf(red[0]), 1e-8f);
}

// ---------------- cosine logits ----------------
__global__ void preds_kernel(const float* __restrict__ emb, const float* __restrict__ protos,
                             const float* __restrict__ protoInv, float* __restrict__ out)
{
    const int b = blockIdx.x / 75, t = blockIdx.x % 75;
    const int tid = threadIdx.x;
    float dot[5] = {0,0,0,0,0};
    float nsq = 0.f;
    const float* e = emb + (size_t)(200 + b*75 + t)*2304;
    for (int d = tid; d < 2304; d += 256) {
        float ev = e[d];
        nsq += ev*ev;
#pragma unroll
        for (int c = 0; c < 5; c++)
            dot[c] = fmaf(ev, protos[(b*5 + c)*2304 + d], dot[c]);
    }
    __shared__ float red[256];
    __shared__ float res[6];
    for (int q = 0; q < 6; q++) {
        red[tid] = (q == 0) ? nsq : dot[q-1];
        __syncthreads();
        for (int s = 128; s > 0; s >>= 1) {
            if (tid < s) red[tid] += red[tid + s];
            __syncthreads();
        }
        if (tid == 0) res[q] = red[0];
        __syncthreads();
    }
    if (tid < 5) {
        float inv_t = 1.f / fmaxf(sqrtf(res[0]), 1e-8f);
        out[(b*75 + t)*5 + tid] = res[1 + tid] * inv_t * protoInv[b*5 + tid];
    }
}

// ---------------- launch ----------------
extern "C" void kernel_launch(void* const* d_in, const int* in_sizes, int n_in,
                              void* d_out, int out_size)
{
    const float* xs = (const float*)d_in[0];
    const float* xt = (const float*)d_in[1];
    const int*   y  = (const int*)  d_in[2];
    const float* W1 = (const float*)d_in[3];
    const float* b1 = (const float*)d_in[4];
    const float* W2 = (const float*)d_in[5];
    const float* b2 = (const float*)d_in[6];
    const float* W3 = (const float*)d_in[7];
    const float* b3 = (const float*)d_in[8];
    const float* W4 = (const float*)d_in[9];
    const float* b4 = (const float*)d_in[10];
    float* out = (float*)d_out;

    float *bufA, *bufB, *bufC, *bufD, *pr, *pi, *w2t;
    cudaGetSymbolAddress((void**)&bufA, g_bufA);
    cudaGetSymbolAddress((void**)&bufB, g_bufB);
    cudaGetSymbolAddress((void**)&bufC, g_bufC);
    cudaGetSymbolAddress((void**)&bufD, g_bufD);
    cudaGetSymbolAddress((void**)&pr,   g_protos);
    cudaGetSymbolAddress((void**)&pi,   g_protoInv);
    cudaGetSymbolAddress((void**)&w2t,  g_w2t);

    static int smem_set = 0;
    if (!smem_set) {
        cudaFuncSetAttribute(conv2_mma, cudaFuncAttributeMaxDynamicSharedMemorySize,
                             C2_SMEMF*4);
        smem_set = 1;
    }

    // prepack conv2 weights
    prepack_w2<<<(9*4096 + 255)/256, 256>>>(W2, w2t);

    // conv1: 3->64, 84->42, NHWC output (exact R1 config otherwise)
    conv_s2_kernel<3,84,42,0, 3,4,3, 32, true><<<dim3(200,14), 256>>>(xs, W1, b1, bufA);
    conv_s2_kernel<3,84,42,0, 3,4,3, 32, true><<<dim3(600,14), 256>>>(xt, W1, b1, bufA + (size_t)200*64*42*42);
    // conv2: mma.sync tf32 implicit GEMM, NHWC in -> NCHW out
    conv2_mma<<<dim3(800,4), 256, C2_SMEMF*4>>>(bufA, w2t, b2, bufB);
    // conv3: 64->64, 21->11, pad_low=1 (exact R1)
    conv_s2_kernel<64,21,11,1, 11,4,8, 31, false><<<dim3(800,1), 248>>>(bufB, W3, b3, bufC);
    // conv4: 64->64, 11->6, pad_low=1 (exact R1)
    conv_s2_kernel<64,11,6,1, 6,2,8, 18, false><<<dim3(800,1), 144>>>(bufC, W4, b4, bufD);
    // head
    protos_kernel<<<40, 256>>>(bufD, y, pr, pi);
    preds_kernel<<<600, 256>>>(bufD, pr, pi, out);
}

// round 10
// speedup vs baseline: 2.7460x; 1.3035x over previous
#include <cuda_runtime.h>
#include <math.h>
#include <stdint.h>

// ---------------- scratch ----------------
__device__ float g_bufA[800L*64*42*42];   // conv1 out (NHWC)
__device__ float g_bufB[800L*64*21*21];   // conv2 out (NHWC)
__device__ float g_bufC[800L*64*11*11];   // conv3 out (NHWC)
__device__ float g_bufD[800L*2304];       // conv4 out (embeddings, NHWC-flat)
__device__ float g_protos[8*5*2304];
__device__ float g_protoInv[8*5];
// prepacked tf32 weights: [tap(9)][cin(64)][cout(64)]
__device__ float g_w2t[9*64*64];
__device__ float g_w3t[9*64*64];
__device__ float g_w4t[9*64*64];

__device__ __forceinline__ float tf32_rna(float x) {
    uint32_t r; asm("cvt.rna.tf32.f32 %0, %1;" : "=r"(r) : "f"(x));
    return __uint_as_float(r);
}

// ---------------- weight prepack (64-cin layers) ----------------
__global__ void prepack_w(const float* __restrict__ w, float* __restrict__ wt)
{
    int gid = blockIdx.x * 256 + threadIdx.x;          // 9*4096
    if (gid >= 9*4096) return;
    int tap  = gid >> 12;
    int r    = gid & 4095;
    int cin  = r >> 6;
    int cout = r & 63;
    wt[gid] = tf32_rna(w[(cout*64 + cin)*9 + tap]);
}

// ---------------- scalar conv1 (EXACT R1) with NHWC out ----------
template<int CIN, int H, int OH, int PADLOW, int OYT, int TPOS, int CK, int PTHREADS>
__global__ void __launch_bounds__(PTHREADS*8)
conv1_kernel(const float* __restrict__ in, const float* __restrict__ wgt,
             const float* __restrict__ bias, float* __restrict__ out)
{
    constexpr int W = H, OW = OH;
    constexpr int RP = 2*OYT + 1;
    constexpr int WP = 2*OW + 1;
    constexpr int IN_SZ = CK*RP*WP;
    constexpr int W_SZ  = 64*CK*9;
    constexpr int NPOS  = OYT*OW;
    constexpr int NT    = PTHREADS*8;

    __shared__ float s_in[IN_SZ];
    __shared__ float s_w[W_SZ];

    const int n   = blockIdx.x;
    const int oy0 = blockIdx.y * OYT;
    const int tid = threadIdx.x;
    const int px  = tid % PTHREADS;
    const int cy  = tid / PTHREADS;

    int  baseoff[TPOS], oyl_arr[TPOS], ox_arr[TPOS];
    bool valid[TPOS];
#pragma unroll
    for (int p = 0; p < TPOS; p++) {
        int pos = px + p*PTHREADS;
        valid[p] = pos < NPOS;
        if (pos >= NPOS) pos = NPOS - 1;
        int oyl = pos / OW;
        int ox  = pos - oyl*OW;
        oyl_arr[p] = oyl; ox_arr[p] = ox;
        baseoff[p] = (2*oyl)*WP + 2*ox;
    }

    float acc[8][TPOS];
#pragma unroll
    for (int i = 0; i < 8; i++)
#pragma unroll
        for (int j = 0; j < TPOS; j++) acc[i][j] = 0.f;

    for (int c0 = 0; c0 < CIN; c0 += CK) {
        for (int idx = tid; idx < IN_SZ; idx += NT) {
            int c   = idx / (RP*WP);
            int rem = idx - c*(RP*WP);
            int r   = rem / WP;
            int s   = rem - r*WP;
            int gr  = 2*oy0 + r - PADLOW;
            int gc  = s - PADLOW;
            float v = 0.f;
            if (gr >= 0 && gr < H && gc >= 0 && gc < W)
                v = in[((n*CIN + c0 + c)*H + gr)*W + gc];
            s_in[idx] = v;
        }
        for (int idx = tid; idx < W_SZ; idx += NT) {
            int cout = idx / (CK*9);
            int rem  = idx - cout*(CK*9);
            s_w[idx] = wgt[(cout*CIN + c0)*9 + rem];
        }
        __syncthreads();

#pragma unroll
        for (int c = 0; c < CK; c++) {
            float xin[TPOS][9];
#pragma unroll
            for (int p = 0; p < TPOS; p++) {
                const float* bp = &s_in[c*(RP*WP) + baseoff[p]];
#pragma unroll
                for (int ky = 0; ky < 3; ky++)
#pragma unroll
                    for (int kx = 0; kx < 3; kx++)
                        xin[p][ky*3 + kx] = bp[ky*WP + kx];
            }
#pragma unroll
            for (int co = 0; co < 8; co++) {
                const float* wq = &s_w[((cy*8 + co)*CK + c)*9];
                float wl[9];
#pragma unroll
                for (int k = 0; k < 9; k++) wl[k] = wq[k];
#pragma unroll
                for (int p = 0; p < TPOS; p++) {
                    float a = acc[co][p];
#pragma unroll
                    for (int k = 0; k < 9; k++) a = fmaf(wl[k], xin[p][k], a);
                    acc[co][p] = a;
                }
            }
        }
        __syncthreads();
    }

    const int oy_valid = (OH - oy0 < OYT) ? (OH - oy0) : OYT;
    float bz[8];
#pragma unroll
    for (int co = 0; co < 8; co++) bz[co] = bias[cy*8 + co];
#pragma unroll
    for (int p = 0; p < TPOS; p++) {
        if (valid[p] && oyl_arr[p] < oy_valid) {
            float4 v0, v1;
            v0.x = fmaxf(acc[0][p]+bz[0], 0.f); v0.y = fmaxf(acc[1][p]+bz[1], 0.f);
            v0.z = fmaxf(acc[2][p]+bz[2], 0.f); v0.w = fmaxf(acc[3][p]+bz[3], 0.f);
            v1.x = fmaxf(acc[4][p]+bz[4], 0.f); v1.y = fmaxf(acc[5][p]+bz[5], 0.f);
            v1.z = fmaxf(acc[6][p]+bz[6], 0.f); v1.w = fmaxf(acc[7][p]+bz[7], 0.f);
            float* op = &out[(((size_t)n*OH + oy0 + oyl_arr[p])*OW + ox_arr[p])*64 + cy*8];
            *(float4*)op       = v0;
            *(float4*)(op + 4) = v1;
        }
    }
}

// ---------------- generic mma.sync tf32 implicit-GEMM conv -----------------
// NHWC in, NHWC out. M = IMGS * MROWS * OW positions (padded to 128),
// N = 64 couts, K = 576 = 9 taps x 64 cin. 8 warps x 32x32 tile.
#define AP 68
#define BP 72
#define MMA_SMEMB ((128*AP + 64*BP + 64)*4)

template<int IH, int OH, int PADLOW, int MROWS, int IMGS, int NIMG>
__global__ void __launch_bounds__(256)
conv_mma(const float* __restrict__ in, const float* __restrict__ wt,
         const float* __restrict__ bias, float* __restrict__ out)
{
    extern __shared__ float smf[];
    float* sA = smf;                 // 128 x 68
    float* sB = smf + 128*AP;        // 64 x 72
    float* sbias = sB + 64*BP;       // 64

    constexpr int OW = OH;
    constexpr int MP = MROWS*OW;

    const int tid  = threadIdx.x;
    const int wid  = tid >> 5;
    const int lane = tid & 31;
    const int n0   = blockIdx.x * IMGS;
    const int oy0  = blockIdx.y * MROWS;

    if (tid < 64) sbias[tid] = bias[tid];

    const int wm = (wid & 3) * 32;
    const int wn = (wid >> 2) * 32;

    float c[2][4][4];
#pragma unroll
    for (int i = 0; i < 2; i++)
#pragma unroll
        for (int j = 0; j < 4; j++)
#pragma unroll
            for (int q = 0; q < 4; q++) c[i][j][q] = 0.f;

    // A staging: 2 threads per position, 32 cins each
    const int p2   = tid >> 1;
    const int half = tid & 1;
    const int img  = p2 / MP;
    const int rem  = p2 - img*MP;
    const int oyl  = rem / OW;
    const int oxp  = rem - oyl*OW;
    const int oy   = oy0 + oyl;
    const int n    = n0 + img;
    const bool pv  = (img < IMGS) && (n < NIMG) && (oy < OH);
    const float* imgbase = in + (size_t)n*IH*IH*64;

    for (int tap = 0; tap < 9; tap++) {
        const int ky = tap / 3, kx = tap - 3*(tap/3);
        const int ry = 2*oy + ky - PADLOW;
        const int rx = 2*oxp + kx - PADLOW;
        const bool v = pv && ((unsigned)ry < (unsigned)IH) && ((unsigned)rx < (unsigned)IH);
        const float* src = imgbase + ((size_t)ry*IH + rx)*64 + half*32;
        float* dstA = sA + p2*AP + half*32;
#pragma unroll
        for (int j = 0; j < 8; j++) {
            float4 x = v ? *(const float4*)(src + 4*j) : make_float4(0.f,0.f,0.f,0.f);
            x.x = tf32_rna(x.x); x.y = tf32_rna(x.y);
            x.z = tf32_rna(x.z); x.w = tf32_rna(x.w);
            *(float4*)(dstA + 4*j) = x;
        }
        {
            const float4* bsrc = (const float4*)(wt + tap*4096);
#pragma unroll
            for (int i = 0; i < 4; i++) {
                int idx = tid + i*256;
                int row = idx >> 4, col4 = idx & 15;
                *(float4*)(sB + row*BP + col4*4) = bsrc[idx];
            }
        }
        __syncthreads();

#pragma unroll
        for (int ks = 0; ks < 8; ks++) {
            const int k0 = ks*8;
            uint32_t a[2][4];
#pragma unroll
            for (int mi = 0; mi < 2; mi++) {
                const float* ap = sA + (wm + mi*16 + (lane>>2))*AP + k0 + (lane&3);
                a[mi][0] = __float_as_uint(ap[0]);
                a[mi][1] = __float_as_uint(ap[8*AP]);
                a[mi][2] = __float_as_uint(ap[4]);
                a[mi][3] = __float_as_uint(ap[8*AP + 4]);
            }
            uint32_t b[4][2];
#pragma unroll
            for (int ni = 0; ni < 4; ni++) {
                const float* bp = sB + (k0 + (lane&3))*BP + wn + ni*8 + (lane>>2);
                b[ni][0] = __float_as_uint(bp[0]);
                b[ni][1] = __float_as_uint(bp[4*BP]);
            }
#pragma unroll
            for (int mi = 0; mi < 2; mi++)
#pragma unroll
                for (int ni = 0; ni < 4; ni++)
                    asm volatile(
                        "mma.sync.aligned.m16n8k8.row.col.f32.tf32.tf32.f32 "
                        "{%0,%1,%2,%3}, {%4,%5,%6,%7}, {%8,%9}, {%0,%1,%2,%3};"
                        : "+f"(c[mi][ni][0]), "+f"(c[mi][ni][1]),
                          "+f"(c[mi][ni][2]), "+f"(c[mi][ni][3])
                        : "r"(a[mi][0]), "r"(a[mi][1]), "r"(a[mi][2]), "r"(a[mi][3]),
                          "r"(b[ni][0]), "r"(b[ni][1]));
        }
        __syncthreads();
    }

    // epilogue: bias + relu, NHWC float2 stores
#pragma unroll
    for (int mi = 0; mi < 2; mi++) {
#pragma unroll
        for (int half_m = 0; half_m < 2; half_m++) {
            const int row = wm + mi*16 + (lane>>2) + half_m*8;
            const int imgE = row / MP;
            const int remE = row - imgE*MP;
            const int oyE  = oy0 + remE/OW;
            const int oxE  = remE - (remE/OW)*OW;
            const int nE   = n0 + imgE;
            if (imgE < IMGS && nE < NIMG && oyE < OH) {
                float* op = out + (((size_t)nE*OH + oyE)*OW + oxE)*64;
#pragma unroll
                for (int ni = 0; ni < 4; ni++) {
                    const int c0 = wn + ni*8 + 2*(lane&3);
                    float2 vv;
                    vv.x = fmaxf(c[mi][ni][half_m*2    ] + sbias[c0    ], 0.f);
                    vv.y = fmaxf(c[mi][ni][half_m*2 + 1] + sbias[c0 + 1], 0.f);
                    *(float2*)(op + c0) = vv;
                }
            }
        }
    }
}

// ---------------- prototypes + inverse norms ----------------
__global__ void protos_kernel(const float* __restrict__ emb, const int* __restrict__ y,
                              float* __restrict__ protos, float* __restrict__ protoInv)
{
    const int b = blockIdx.x / 5, c = blockIdx.x % 5;
    const int tid = threadIdx.x;
    __shared__ int sels[25];
    if (tid < 25) sels[tid] = ((y[b*25 + tid] % 5) == c) ? 1 : 0;
    __syncthreads();

    float sq = 0.f;
    for (int d = tid; d < 2304; d += 256) {
        float v = 0.f;
#pragma unroll
        for (int s = 0; s < 25; s++)
            if (sels[s]) v += emb[(b*25 + s)*2304 + d];
        v = v / 5.0f;
        protos[(b*5 + c)*2304 + d] = v;
        sq += v*v;
    }
    __shared__ float red[256];
    red[tid] = sq; __syncthreads();
    for (int s = 128; s > 0; s >>= 1) {
        if (tid < s) red[tid] += red[tid + s];
        __syncthreads();
    }
    if (tid == 0) protoInv[b*5 + c] = 1.f / fmaxf(sqrtf(red[0]), 1e-8f);
}

// ---------------- cosine logits ----------------
__global__ void preds_kernel(const float* __restrict__ emb, const float* __restrict__ protos,
                             const float* __restrict__ protoInv, float* __restrict__ out)
{
    const int b = blockIdx.x / 75, t = blockIdx.x % 75;
    const int tid = threadIdx.x;
    float dot[5] = {0,0,0,0,0};
    float nsq = 0.f;
    const float* e = emb + (size_t)(200 + b*75 + t)*2304;
    for (int d = tid; d < 2304; d += 256) {
        float ev = e[d];
        nsq += ev*ev;
#pragma unroll
        for (int c = 0; c < 5; c++)
            dot[c] = fmaf(ev, protos[(b*5 + c)*2304 + d], dot[c]);
    }
    __shared__ float red[256];
    __shared__ float res[6];
    for (int q = 0; q < 6; q++) {
        red[tid] = (q == 0) ? nsq : dot[q-1];
        __syncthreads();
        for (int s = 128; s > 0; s >>= 1) {
            if (tid < s) red[tid] += red[tid + s];
            __syncthreads();
        }
        if (tid == 0) res[q] = red[0];
        __syncthreads();
    }
    if (tid < 5) {
        float inv_t = 1.f / fmaxf(sqrtf(res[0]), 1e-8f);
        out[(b*75 + t)*5 + tid] = res[1 + tid] * inv_t * protoInv[b*5 + tid];
    }
}

// ---------------- launch ----------------
extern "C" void kernel_launch(void* const* d_in, const int* in_sizes, int n_in,
                              void* d_out, int out_size)
{
    const float* xs = (const float*)d_in[0];
    const float* xt = (const float*)d_in[1];
    const int*   y  = (const int*)  d_in[2];
    const float* W1 = (const float*)d_in[3];
    const float* b1 = (const float*)d_in[4];
    const float* W2 = (const float*)d_in[5];
    const float* b2 = (const float*)d_in[6];
    const float* W3 = (const float*)d_in[7];
    const float* b3 = (const float*)d_in[8];
    const float* W4 = (const float*)d_in[9];
    const float* b4 = (const float*)d_in[10];
    float* out = (float*)d_out;

    float *bufA, *bufB, *bufC, *bufD, *pr, *pi, *w2t, *w3t, *w4t;
    cudaGetSymbolAddress((void**)&bufA, g_bufA);
    cudaGetSymbolAddress((void**)&bufB, g_bufB);
    cudaGetSymbolAddress((void**)&bufC, g_bufC);
    cudaGetSymbolAddress((void**)&bufD, g_bufD);
    cudaGetSymbolAddress((void**)&pr,   g_protos);
    cudaGetSymbolAddress((void**)&pi,   g_protoInv);
    cudaGetSymbolAddress((void**)&w2t,  g_w2t);
    cudaGetSymbolAddress((void**)&w3t,  g_w3t);
    cudaGetSymbolAddress((void**)&w4t,  g_w4t);

    static int smem_set = 0;
    if (!smem_set) {
        cudaFuncSetAttribute(conv_mma<42,21,0, 6,1,800>,
                             cudaFuncAttributeMaxDynamicSharedMemorySize, MMA_SMEMB);
        cudaFuncSetAttribute(conv_mma<21,11,1, 11,1,800>,
                             cudaFuncAttributeMaxDynamicSharedMemorySize, MMA_SMEMB);
        cudaFuncSetAttribute(conv_mma<11,6,1, 6,3,800>,
                             cudaFuncAttributeMaxDynamicSharedMemorySize, MMA_SMEMB);
        smem_set = 1;
    }

    // prepack tf32 weights for conv2/3/4
    prepack_w<<<(9*4096 + 255)/256, 256>>>(W2, w2t);
    prepack_w<<<(9*4096 + 255)/256, 256>>>(W3, w3t);
    prepack_w<<<(9*4096 + 255)/256, 256>>>(W4, w4t);

    // conv1: scalar R1, NCHW in -> NHWC out
    conv1_kernel<3,84,42,0, 3,4,3, 32><<<dim3(200,14), 256>>>(xs, W1, b1, bufA);
    conv1_kernel<3,84,42,0, 3,4,3, 32><<<dim3(600,14), 256>>>(xt, W1, b1, bufA + (size_t)200*64*42*42);
    // conv2: 42->21, pad 0, 6 rows/CTA, 1 img/CTA
    conv_mma<42,21,0, 6,1,800><<<dim3(800,4), 256, MMA_SMEMB>>>(bufA, w2t, b2, bufB);
    // conv3: 21->11, pad 1, whole image (121 pos), 1 img/CTA
    conv_mma<21,11,1, 11,1,800><<<dim3(800,1), 256, MMA_SMEMB>>>(bufB, w3t, b3, bufC);
    // conv4: 11->6, pad 1, whole image, 3 imgs/CTA (108 pos)
    conv_mma<11,6,1, 6,3,800><<<dim3(267,1), 256, MMA_SMEMB>>>(bufC, w4t, b4, bufD);
    // head
    protos_kernel<<<40, 256>>>(bufD, y, pr, pi);
    preds_kernel<<<600, 256>>>(bufD, pr, pi, out);
}

// round 11
// speedup vs baseline: 3.3788x; 1.2304x over previous
#include <cuda_runtime.h>
#include <math.h>
#include <stdint.h>

// ---------------- scratch ----------------
__device__ float g_bufA[800L*64*42*42];   // conv1 out (NHWC)
__device__ float g_bufB[800L*64*21*21];   // conv2 out (NHWC)
__device__ float g_bufC[800L*64*11*11];   // conv3 out (NHWC)
__device__ float g_bufD[800L*2304];       // conv4 out (embeddings, NHWC-flat)
__device__ float g_protos[8*5*2304];
__device__ float g_protoInv[8*5];
// prepacked tf32 weights
__device__ float g_w1t[32*64];            // conv1: [k(32)][cout], k = c*9+tap, rows 27..31 zero
__device__ float g_w2t[9*64*64];          // [tap][cin][cout]
__device__ float g_w3t[9*64*64];
__device__ float g_w4t[9*64*64];

__device__ __forceinline__ float tf32_rna(float x) {
    uint32_t r; asm("cvt.rna.tf32.f32 %0, %1;" : "=r"(r) : "f"(x));
    return __uint_as_float(r);
}

// ---------------- weight prepacks ----------------
__global__ void prepack_w(const float* __restrict__ w, float* __restrict__ wt)
{
    int gid = blockIdx.x * 256 + threadIdx.x;          // 9*4096
    if (gid >= 9*4096) return;
    int tap  = gid >> 12;
    int r    = gid & 4095;
    int cin  = r >> 6;
    int cout = r & 63;
    wt[gid] = tf32_rna(w[(cout*64 + cin)*9 + tap]);
}

__global__ void prepack_w1(const float* __restrict__ w, float* __restrict__ wt)
{
    int gid = blockIdx.x * 256 + threadIdx.x;          // 32*64
    if (gid >= 32*64) return;
    int k    = gid >> 6;
    int cout = gid & 63;
    float v = 0.f;
    if (k < 27) {
        int c = k / 9, tap = k - 9*c;
        v = tf32_rna(w[(cout*3 + c)*9 + tap]);
    }
    wt[gid] = v;
}

// ---------------- conv1: mma.sync tf32, NCHW in -> NHWC out ----------------
// CTA: one image, 3 output rows -> M=126 (pad 128), N=64, K=27 pad 32.
#define A1P 36
#define B1P 72

__global__ void __launch_bounds__(256)
conv1_mma(const float* __restrict__ in, const float* __restrict__ wt,
          const float* __restrict__ bias, float* __restrict__ out)
{
    __shared__ float sA[128*A1P];
    __shared__ float sB[32*B1P];
    __shared__ float sbias[64];

    const int tid  = threadIdx.x;
    const int wid  = tid >> 5;
    const int lane = tid & 31;
    const int n    = blockIdx.x;
    const int oy0  = blockIdx.y * 3;

    if (tid < 64) sbias[tid] = bias[tid];

    // ---- stage A: threads 0..127 gather one position each (27 taps) ----
    if (tid < 128) {
        const int p   = tid;
        const int oyl = p / 42;
        const int oxp = p - oyl*42;
        const int oy  = oy0 + oyl;
        const bool pv = p < 126;
        const float* ib = in + (size_t)n*3*84*84;
        float* dst = sA + p*A1P;
#pragma unroll
        for (int c = 0; c < 3; c++) {
#pragma unroll
            for (int ky = 0; ky < 3; ky++) {
#pragma unroll
                for (int kx = 0; kx < 3; kx++) {
                    const int ry = 2*oy + ky;        // pad_low = 0
                    const int rx = 2*oxp + kx;
                    float v = 0.f;
                    if (pv && ry < 84 && rx < 84)
                        v = ib[(c*84 + ry)*84 + rx];
                    dst[c*9 + ky*3 + kx] = tf32_rna(v);
                }
            }
        }
        dst[27] = 0.f; dst[28] = 0.f; dst[29] = 0.f; dst[30] = 0.f; dst[31] = 0.f;
    } else {
        // ---- stage B: threads 128..255, 32x64 prepacked ----
        const int t = tid - 128;
        const float4* bsrc = (const float4*)wt;
#pragma unroll
        for (int i = 0; i < 4; i++) {
            int idx = t + i*128;             // 0..511
            int row = idx >> 4, col4 = idx & 15;
            *(float4*)(sB + row*B1P + col4*4) = bsrc[idx];
        }
    }
    __syncthreads();

    const int wm = (wid & 3) * 32;
    const int wn = (wid >> 2) * 32;

    float c[2][4][4];
#pragma unroll
    for (int i = 0; i < 2; i++)
#pragma unroll
        for (int j = 0; j < 4; j++)
#pragma unroll
            for (int q = 0; q < 4; q++) c[i][j][q] = 0.f;

#pragma unroll
    for (int ks = 0; ks < 4; ks++) {
        const int k0 = ks*8;
        uint32_t a[2][4];
#pragma unroll
        for (int mi = 0; mi < 2; mi++) {
            const float* ap = sA + (wm + mi*16 + (lane>>2))*A1P + k0 + (lane&3);
            a[mi][0] = __float_as_uint(ap[0]);
            a[mi][1] = __float_as_uint(ap[8*A1P]);
            a[mi][2] = __float_as_uint(ap[4]);
            a[mi][3] = __float_as_uint(ap[8*A1P + 4]);
        }
        uint32_t b[4][2];
#pragma unroll
        for (int ni = 0; ni < 4; ni++) {
            const float* bp = sB + (k0 + (lane&3))*B1P + wn + ni*8 + (lane>>2);
            b[ni][0] = __float_as_uint(bp[0]);
            b[ni][1] = __float_as_uint(bp[4*B1P]);
        }
#pragma unroll
        for (int mi = 0; mi < 2; mi++)
#pragma unroll
            for (int ni = 0; ni < 4; ni++)
                asm volatile(
                    "mma.sync.aligned.m16n8k8.row.col.f32.tf32.tf32.f32 "
                    "{%0,%1,%2,%3}, {%4,%5,%6,%7}, {%8,%9}, {%0,%1,%2,%3};"
                    : "+f"(c[mi][ni][0]), "+f"(c[mi][ni][1]),
                      "+f"(c[mi][ni][2]), "+f"(c[mi][ni][3])
                    : "r"(a[mi][0]), "r"(a[mi][1]), "r"(a[mi][2]), "r"(a[mi][3]),
                      "r"(b[ni][0]), "r"(b[ni][1]));
    }

    // epilogue: bias + relu, NHWC float2 stores
#pragma unroll
    for (int mi = 0; mi < 2; mi++) {
#pragma unroll
        for (int half_m = 0; half_m < 2; half_m++) {
            const int row = wm + mi*16 + (lane>>2) + half_m*8;
            if (row < 126) {
                const int oyE = oy0 + row/42;
                const int oxE = row - (row/42)*42;
                float* op = out + (((size_t)n*42 + oyE)*42 + oxE)*64;
#pragma unroll
                for (int ni = 0; ni < 4; ni++) {
                    const int c0 = wn + ni*8 + 2*(lane&3);
                    float2 vv;
                    vv.x = fmaxf(c[mi][ni][half_m*2    ] + sbias[c0    ], 0.f);
                    vv.y = fmaxf(c[mi][ni][half_m*2 + 1] + sbias[c0 + 1], 0.f);
                    *(float2*)(op + c0) = vv;
                }
            }
        }
    }
}

// ---------------- generic mma.sync tf32 implicit-GEMM conv -----------------
#define AP 68
#define BP 72
#define MMA_SMEMB ((128*AP + 64*BP + 64)*4)

template<int IH, int OH, int PADLOW, int MROWS, int IMGS, int NIMG>
__global__ void __launch_bounds__(256)
conv_mma(const float* __restrict__ in, const float* __restrict__ wt,
         const float* __restrict__ bias, float* __restrict__ out)
{
    extern __shared__ float smf[];
    float* sA = smf;
    float* sB = smf + 128*AP;
    float* sbias = sB + 64*BP;

    constexpr int OW = OH;
    constexpr int MP = MROWS*OW;

    const int tid  = threadIdx.x;
    const int wid  = tid >> 5;
    const int lane = tid & 31;
    const int n0   = blockIdx.x * IMGS;
    const int oy0  = blockIdx.y * MROWS;

    if (tid < 64) sbias[tid] = bias[tid];

    const int wm = (wid & 3) * 32;
    const int wn = (wid >> 2) * 32;

    float c[2][4][4];
#pragma unroll
    for (int i = 0; i < 2; i++)
#pragma unroll
        for (int j = 0; j < 4; j++)
#pragma unroll
            for (int q = 0; q < 4; q++) c[i][j][q] = 0.f;

    const int p2   = tid >> 1;
    const int half = tid & 1;
    const int img  = p2 / MP;
    const int rem  = p2 - img*MP;
    const int oyl  = rem / OW;
    const int oxp  = rem - oyl*OW;
    const int oy   = oy0 + oyl;
    const int n    = n0 + img;
    const bool pv  = (img < IMGS) && (n < NIMG) && (oy < OH);
    const float* imgbase = in + (size_t)n*IH*IH*64;

    for (int tap = 0; tap < 9; tap++) {
        const int ky = tap / 3, kx = tap - 3*(tap/3);
        const int ry = 2*oy + ky - PADLOW;
        const int rx = 2*oxp + kx - PADLOW;
        const bool v = pv && ((unsigned)ry < (unsigned)IH) && ((unsigned)rx < (unsigned)IH);
        const float* src = imgbase + ((size_t)ry*IH + rx)*64 + half*32;
        float* dstA = sA + p2*AP + half*32;
#pragma unroll
        for (int j = 0; j < 8; j++) {
            float4 x = v ? *(const float4*)(src + 4*j) : make_float4(0.f,0.f,0.f,0.f);
            x.x = tf32_rna(x.x); x.y = tf32_rna(x.y);
            x.z = tf32_rna(x.z); x.w = tf32_rna(x.w);
            *(float4*)(dstA + 4*j) = x;
        }
        {
            const float4* bsrc = (const float4*)(wt + tap*4096);
#pragma unroll
            for (int i = 0; i < 4; i++) {
                int idx = tid + i*256;
                int row = idx >> 4, col4 = idx & 15;
                *(float4*)(sB + row*BP + col4*4) = bsrc[idx];
            }
        }
        __syncthreads();

#pragma unroll
        for (int ks = 0; ks < 8; ks++) {
            const int k0 = ks*8;
            uint32_t a[2][4];
#pragma unroll
            for (int mi = 0; mi < 2; mi++) {
                const float* ap = sA + (wm + mi*16 + (lane>>2))*AP + k0 + (lane&3);
                a[mi][0] = __float_as_uint(ap[0]);
                a[mi][1] = __float_as_uint(ap[8*AP]);
                a[mi][2] = __float_as_uint(ap[4]);
                a[mi][3] = __float_as_uint(ap[8*AP + 4]);
            }
            uint32_t b[4][2];
#pragma unroll
            for (int ni = 0; ni < 4; ni++) {
                const float* bp = sB + (k0 + (lane&3))*BP + wn + ni*8 + (lane>>2);
                b[ni][0] = __float_as_uint(bp[0]);
                b[ni][1] = __float_as_uint(bp[4*BP]);
            }
#pragma unroll
            for (int mi = 0; mi < 2; mi++)
#pragma unroll
                for (int ni = 0; ni < 4; ni++)
                    asm volatile(
                        "mma.sync.aligned.m16n8k8.row.col.f32.tf32.tf32.f32 "
                        "{%0,%1,%2,%3}, {%4,%5,%6,%7}, {%8,%9}, {%0,%1,%2,%3};"
                        : "+f"(c[mi][ni][0]), "+f"(c[mi][ni][1]),
                          "+f"(c[mi][ni][2]), "+f"(c[mi][ni][3])
                        : "r"(a[mi][0]), "r"(a[mi][1]), "r"(a[mi][2]), "r"(a[mi][3]),
                          "r"(b[ni][0]), "r"(b[ni][1]));
        }
        __syncthreads();
    }

#pragma unroll
    for (int mi = 0; mi < 2; mi++) {
#pragma unroll
        for (int half_m = 0; half_m < 2; half_m++) {
            const int row = wm + mi*16 + (lane>>2) + half_m*8;
            const int imgE = row / MP;
            const int remE = row - imgE*MP;
            const int oyE  = oy0 + remE/OW;
            const int oxE  = remE - (remE/OW)*OW;
            const int nE   = n0 + imgE;
            if (imgE < IMGS && nE < NIMG && oyE < OH) {
                float* op = out + (((size_t)nE*OH + oyE)*OW + oxE)*64;
#pragma unroll
                for (int ni = 0; ni < 4; ni++) {
                    const int c0 = wn + ni*8 + 2*(lane&3);
                    float2 vv;
                    vv.x = fmaxf(c[mi][ni][half_m*2    ] + sbias[c0    ], 0.f);
                    vv.y = fmaxf(c[mi][ni][half_m*2 + 1] + sbias[c0 + 1], 0.f);
                    *(float2*)(op + c0) = vv;
                }
            }
        }
    }
}

// ---------------- prototypes + inverse norms ----------------
__global__ void protos_kernel(const float* __restrict__ emb, const int* __restrict__ y,
                              float* __restrict__ protos, float* __restrict__ protoInv)
{
    const int b = blockIdx.x / 5, c = blockIdx.x % 5;
    const int tid = threadIdx.x;
    __shared__ int sels[25];
    if (tid < 25) sels[tid] = ((y[b*25 + tid] % 5) == c) ? 1 : 0;
    __syncthreads();

    float sq = 0.f;
    for (int d = tid; d < 2304; d += 256) {
        float v = 0.f;
#pragma unroll
        for (int s = 0; s < 25; s++)
            if (sels[s]) v += emb[(b*25 + s)*2304 + d];
        v = v / 5.0f;
        protos[(b*5 + c)*2304 + d] = v;
        sq += v*v;
    }
    __shared__ float red[256];
    red[tid] = sq; __syncthreads();
    for (int s = 128; s > 0; s >>= 1) {
        if (tid < s) red[tid] += red[tid + s];
        __syncthreads();
    }
    if (tid == 0) protoInv[b*5 + c] = 1.f / fmaxf(sqrtf(red[0]), 1e-8f);
}

// ---------------- cosine logits ----------------
__global__ void preds_kernel(const float* __restrict__ emb, const float* __restrict__ protos,
                             const float* __restrict__ protoInv, float* __restrict__ out)
{
    const int b = blockIdx.x / 75, t = blockIdx.x % 75;
    const int tid = threadIdx.x;
    float dot[5] = {0,0,0,0,0};
    float nsq = 0.f;
    const float* e = emb + (size_t)(200 + b*75 + t)*2304;
    for (int d = tid; d < 2304; d += 256) {
        float ev = e[d];
        nsq += ev*ev;
#pragma unroll
        for (int c = 0; c < 5; c++)
            dot[c] = fmaf(ev, protos[(b*5 + c)*2304 + d], dot[c]);
    }
    __shared__ float red[256];
    __shared__ float res[6];
    for (int q = 0; q < 6; q++) {
        red[tid] = (q == 0) ? nsq : dot[q-1];
        __syncthreads();
        for (int s = 128; s > 0; s >>= 1) {
            if (tid < s) red[tid] += red[tid + s];
            __syncthreads();
        }
        if (tid == 0) res[q] = red[0];
        __syncthreads();
    }
    if (tid < 5) {
        float inv_t = 1.f / fmaxf(sqrtf(res[0]), 1e-8f);
        out[(b*75 + t)*5 + tid] = res[1 + tid] * inv_t * protoInv[b*5 + tid];
    }
}

// ---------------- launch ----------------
extern "C" void kernel_launch(void* const* d_in, const int* in_sizes, int n_in,
                              void* d_out, int out_size)
{
    const float* xs = (const float*)d_in[0];
    const float* xt = (const float*)d_in[1];
    const int*   y  = (const int*)  d_in[2];
    const float* W1 = (const float*)d_in[3];
    const float* b1 = (const float*)d_in[4];
    const float* W2 = (const float*)d_in[5];
    const float* b2 = (const float*)d_in[6];
    const float* W3 = (const float*)d_in[7];
    const float* b3 = (const float*)d_in[8];
    const float* W4 = (const float*)d_in[9];
    const float* b4 = (const float*)d_in[10];
    float* out = (float*)d_out;

    float *bufA, *bufB, *bufC, *bufD, *pr, *pi, *w1t, *w2t, *w3t, *w4t;
    cudaGetSymbolAddress((void**)&bufA, g_bufA);
    cudaGetSymbolAddress((void**)&bufB, g_bufB);
    cudaGetSymbolAddress((void**)&bufC, g_bufC);
    cudaGetSymbolAddress((void**)&bufD, g_bufD);
    cudaGetSymbolAddress((void**)&pr,   g_protos);
    cudaGetSymbolAddress((void**)&pi,   g_protoInv);
    cudaGetSymbolAddress((void**)&w1t,  g_w1t);
    cudaGetSymbolAddress((void**)&w2t,  g_w2t);
    cudaGetSymbolAddress((void**)&w3t,  g_w3t);
    cudaGetSymbolAddress((void**)&w4t,  g_w4t);

    static int smem_set = 0;
    if (!smem_set) {
        cudaFuncSetAttribute(conv_mma<42,21,0, 6,1,800>,
                             cudaFuncAttributeMaxDynamicSharedMemorySize, MMA_SMEMB);
        cudaFuncSetAttribute(conv_mma<21,11,1, 11,1,800>,
                             cudaFuncAttributeMaxDynamicSharedMemorySize, MMA_SMEMB);
        cudaFuncSetAttribute(conv_mma<11,6,1, 6,3,800>,
                             cudaFuncAttributeMaxDynamicSharedMemorySize, MMA_SMEMB);
        smem_set = 1;
    }

    // prepack tf32 weights
    prepack_w1<<<(32*64 + 255)/256, 256>>>(W1, w1t);
    prepack_w<<<(9*4096 + 255)/256, 256>>>(W2, w2t);
    prepack_w<<<(9*4096 + 255)/256, 256>>>(W3, w3t);
    prepack_w<<<(9*4096 + 255)/256, 256>>>(W4, w4t);

    // conv1: mma, NCHW in -> NHWC out (support then target)
    conv1_mma<<<dim3(200,14), 256>>>(xs, w1t, b1, bufA);
    conv1_mma<<<dim3(600,14), 256>>>(xt, w1t, b1, bufA + (size_t)200*64*42*42);
    // conv2: 42->21, pad 0
    conv_mma<42,21,0, 6,1,800><<<dim3(800,4), 256, MMA_SMEMB>>>(bufA, w2t, b2, bufB);
    // conv3: 21->11, pad 1
    conv_mma<21,11,1, 11,1,800><<<dim3(800,1), 256, MMA_SMEMB>>>(bufB, w3t, b3, bufC);
    // conv4: 11->6, pad 1, 3 imgs/CTA
    conv_mma<11,6,1, 6,3,800><<<dim3(267,1), 256, MMA_SMEMB>>>(bufC, w4t, b4, bufD);
    // head
    protos_kernel<<<40, 256>>>(bufD, y, pr, pi);
    preds_kernel<<<600, 256>>>(bufD, pr, pi, out);
}